// round 10
// baseline (speedup 1.0000x reference)
#include <cuda_runtime.h>
#include <cuda_bf16.h>
#include <stdint.h>
#include <math.h>

// Problem constants
#define BATCH 2
#define SEQ   2048
#define CDIM  768
#define NHEAD 12
#define HDIM  64
#define BHTOT (BATCH*NHEAD)          // 24
#define MROWS (BATCH*SEQ)            // 4096
#define QKVN  (3*CDIM)               // 2304

// ---------------- scratch (device globals; no allocation allowed) -------------
__device__ float g_qkv[(size_t)MROWS * QKVN];
__device__ float g_q[(size_t)BHTOT * SEQ * HDIM];
__device__ float g_k[(size_t)BHTOT * SEQ * HDIM];
__device__ float g_v[(size_t)BHTOT * SEQ * HDIM];
__device__ float g_attn[(size_t)MROWS * CDIM];
__device__ float g_xr[(size_t)MROWS * CDIM];
__device__ float g_wqr[(size_t)CDIM * QKVN];
__device__ float g_wpr[(size_t)CDIM * CDIM];

// ---------------- helpers ------------------------------------------------------
__device__ __forceinline__ uint32_t tf32r(float f) {
    uint32_t u; asm("cvt.rna.tf32.f32 %0, %1;" : "=r"(u) : "f"(f)); return u;
}
__device__ __forceinline__ float tf32f(float f) { return __uint_as_float(tf32r(f)); }
__device__ __forceinline__ float ex2f(float x) {
    float y; asm("ex2.approx.f32 %0, %1;" : "=f"(y) : "f"(x)); return y;
}
__device__ __forceinline__ void mma8(float* c, const uint32_t* a, uint32_t b0, uint32_t b1) {
    asm volatile(
        "mma.sync.aligned.m16n8k8.row.col.f32.tf32.tf32.f32 "
        "{%0,%1,%2,%3}, {%4,%5,%6,%7}, {%8,%9}, {%0,%1,%2,%3};\n"
        : "+f"(c[0]), "+f"(c[1]), "+f"(c[2]), "+f"(c[3])
        : "r"(a[0]), "r"(a[1]), "r"(a[2]), "r"(a[3]), "r"(b0), "r"(b1));
}
__device__ __forceinline__ void cp_async16(void* dst_smem, const void* src_gmem) {
    uint32_t d = (uint32_t)__cvta_generic_to_shared(dst_smem);
    asm volatile("cp.async.cg.shared.global [%0], [%1], 16;\n" :: "r"(d), "l"(src_gmem));
}
__device__ __forceinline__ void cp_commit() { asm volatile("cp.async.commit_group;\n"); }
__device__ __forceinline__ void cp_wait1()  { asm volatile("cp.async.wait_group 1;\n"); }

__device__ __forceinline__ void pfrag(const float* c, int srcA, int srcB, bool odd,
                                      uint32_t* a) {
    float v00 = __shfl_sync(0xffffffffu, c[0], srcA);
    float v01 = __shfl_sync(0xffffffffu, c[1], srcA);
    float v10 = __shfl_sync(0xffffffffu, c[2], srcA);
    float v11 = __shfl_sync(0xffffffffu, c[3], srcA);
    float w00 = __shfl_sync(0xffffffffu, c[0], srcB);
    float w01 = __shfl_sync(0xffffffffu, c[1], srcB);
    float w10 = __shfl_sync(0xffffffffu, c[2], srcB);
    float w11 = __shfl_sync(0xffffffffu, c[3], srcB);
    a[0] = __float_as_uint(odd ? v01 : v00);
    a[1] = __float_as_uint(odd ? v11 : v10);
    a[2] = __float_as_uint(odd ? w01 : w00);
    a[3] = __float_as_uint(odd ? w11 : w10);
}

// ---------------- prep: round fp32 -> tf32 bits in gmem -------------------------
__global__ __launch_bounds__(256) void round_tf32(
    const float* __restrict__ src, float* __restrict__ dst, int n4)
{
    int i = blockIdx.x * blockDim.x + threadIdx.x;
    if (i >= n4) return;
    float4 v = *reinterpret_cast<const float4*>(src + (size_t)i * 4);
    v.x = tf32f(v.x); v.y = tf32f(v.y); v.z = tf32f(v.z); v.w = tf32f(v.w);
    *reinterpret_cast<float4*>(dst + (size_t)i * 4) = v;
}

// ---------------- TF32 tensor-core SGEMM + bias (BK=32, 3-stage cp.async) -------
#define AS_STR 36
#define BS_STR 136
#define STAGE_WORDS (128*AS_STR + 32*BS_STR)   // 8960
#define SG_SMEM (3*STAGE_WORDS*4)              // 107520 B

__global__ __launch_bounds__(256) void sgemm_tf32(
    int M, int N, int K,
    const float* __restrict__ A, const float* __restrict__ B,
    const float* __restrict__ bias, float* __restrict__ C)
{
    extern __shared__ uint32_t smw[];

    const int tid  = threadIdx.x;
    const int warp = tid >> 5;
    const int lane = tid & 31;
    const int g = lane >> 2, t = lane & 3;
    const int warp_m = warp >> 2;
    const int warp_n = warp & 3;
    const int brow = blockIdx.y, bcol = blockIdx.x;

    const float* Ablk = A + (size_t)brow * 128 * K;
    const float* Bblk = B + (size_t)bcol * 128;
    const int ktiles = K >> 5;

    float acc[4][4][4];
    #pragma unroll
    for (int mt = 0; mt < 4; mt++)
        #pragma unroll
        for (int nt = 0; nt < 4; nt++)
            #pragma unroll
            for (int j = 0; j < 4; j++) acc[mt][nt][j] = 0.f;

    auto stage = [&](int kt, int s) {
        uint32_t* As = smw + s * STAGE_WORDS;
        uint32_t* Bs = As + 128 * AS_STR;
        #pragma unroll
        for (int j = 0; j < 4; j++) {
            int f = j * 256 + tid;
            int r = f >> 3, c4 = (f & 7) << 2;
            cp_async16(&As[r * AS_STR + c4], Ablk + (size_t)r * K + kt * 32 + c4);
        }
        #pragma unroll
        for (int j = 0; j < 4; j++) {
            int f = j * 256 + tid;
            int kr = f >> 5, n4 = (f & 31) << 2;
            cp_async16(&Bs[kr * BS_STR + n4], Bblk + (size_t)(kt * 32 + kr) * N + n4);
        }
    };

    stage(0, 0); cp_commit();
    stage(1, 1); cp_commit();

    for (int kt = 0; kt < ktiles; kt++) {
        cp_wait1();
        __syncthreads();
        if (kt + 2 < ktiles) stage(kt + 2, (kt + 2) % 3);
        cp_commit();

        const uint32_t* As = smw + (kt % 3) * STAGE_WORDS;
        const uint32_t* Bs = As + 128 * AS_STR;

        #pragma unroll
        for (int s = 0; s < 4; s++) {
            const int ko = s * 8;
            uint32_t a[4][4], bf[4][2];
            #pragma unroll
            for (int mt = 0; mt < 4; mt++) {
                const int r = warp_m * 64 + mt * 16 + g;
                a[mt][0] = As[r * AS_STR + ko + t];
                a[mt][1] = As[(r + 8) * AS_STR + ko + t];
                a[mt][2] = As[r * AS_STR + ko + t + 4];
                a[mt][3] = As[(r + 8) * AS_STR + ko + t + 4];
            }
            #pragma unroll
            for (int nt = 0; nt < 4; nt++) {
                const int c = warp_n * 32 + nt * 8 + g;
                bf[nt][0] = Bs[(ko + t) * BS_STR + c];
                bf[nt][1] = Bs[(ko + t + 4) * BS_STR + c];
            }
            #pragma unroll
            for (int mt = 0; mt < 4; mt++)
                #pragma unroll
                for (int nt = 0; nt < 4; nt++)
                    mma8(acc[mt][nt], a[mt], bf[nt][0], bf[nt][1]);
        }
    }

    #pragma unroll
    for (int mt = 0; mt < 4; mt++) {
        const int r0 = brow * 128 + warp_m * 64 + mt * 16 + g;
        #pragma unroll
        for (int nt = 0; nt < 4; nt++) {
            const int c = bcol * 128 + warp_n * 32 + nt * 8 + 2 * t;
            float b0 = bias[c], b1 = bias[c + 1];
            float2 v0 = { acc[mt][nt][0] + b0, acc[mt][nt][1] + b1 };
            float2 v1 = { acc[mt][nt][2] + b0, acc[mt][nt][3] + b1 };
            *reinterpret_cast<float2*>(C + (size_t)r0 * N + c) = v0;
            *reinterpret_cast<float2*>(C + (size_t)(r0 + 8) * N + c) = v1;
        }
    }
}

// --------- QKV post: RMSNorm(q,k) + RoPE(q,k) + scale(q), scatter, tf32-round --
__global__ __launch_bounds__(256) void qkv_post(
    const float* __restrict__ qkv,
    const float* __restrict__ cosb, const float* __restrict__ sinb,
    const float* __restrict__ qw,   const float* __restrict__ kw,
    float* __restrict__ Q, float* __restrict__ K, float* __restrict__ V)
{
    int warp = (blockIdx.x * blockDim.x + threadIdx.x) >> 5;
    int lane = threadIdx.x & 31;
    const int NW = BATCH * SEQ * NHEAD;
    if (warp >= NW) return;
    int h = warp % NHEAD;
    int n = (warp / NHEAD) % SEQ;
    int b = warp / (NHEAD * SEQ);

    const float* row = qkv + (size_t)(b * SEQ + n) * QKVN;
    float q0 = row[h * 64 + lane],            q1 = row[h * 64 + lane + 32];
    float k0 = row[CDIM + h * 64 + lane],     k1 = row[CDIM + h * 64 + lane + 32];
    float v0 = row[2 * CDIM + h * 64 + lane], v1 = row[2 * CDIM + h * 64 + lane + 32];

    float sq = q0 * q0 + q1 * q1;
    float sk = k0 * k0 + k1 * k1;
    #pragma unroll
    for (int o = 16; o > 0; o >>= 1) {
        sq += __shfl_xor_sync(0xffffffffu, sq, o);
        sk += __shfl_xor_sync(0xffffffffu, sk, o);
    }
    float rq = rsqrtf(sq * (1.0f / 64.0f) + 1e-6f);
    float rk = rsqrtf(sk * (1.0f / 64.0f) + 1e-6f);
    q0 *= rq * qw[lane]; q1 *= rq * qw[lane + 32];
    k0 *= rk * kw[lane]; k1 *= rk * kw[lane + 32];

    float c0 = cosb[n * 64 + lane], c1 = cosb[n * 64 + lane + 32];
    float s0 = sinb[n * 64 + lane], s1 = sinb[n * 64 + lane + 32];
    float qr0 = q0 * c0 - q1 * s0;
    float qr1 = q1 * c1 + q0 * s1;
    float kr0 = k0 * c0 - k1 * s0;
    float kr1 = k1 * c1 + k0 * s1;

    const float scale = 0.125f * 1.4426950408889634f;
    int bh = b * NHEAD + h;
    float* qo = Q + ((size_t)bh * SEQ + n) * 64;
    float* ko = K + ((size_t)bh * SEQ + n) * 64;
    float* vo = V + ((size_t)bh * SEQ + n) * 64;
    qo[lane] = tf32f(qr0 * scale); qo[lane + 32] = tf32f(qr1 * scale);
    ko[lane] = tf32f(kr0);         ko[lane + 32] = tf32f(kr1);
    vo[lane] = tf32f(v0);          vo[lane + 32] = tf32f(v1);
}

// ---------------- TF32 flash attention: 8 warps x 16 q-rows ---------------------
// CTA: 256 threads, Bq=128, Bk=64, d=64. Warp w owns rows [16w, 16w+16).
// 2 CTAs/SM -> 4 warps/SMSP. P in registers via shfl permute.
#define BQ 128
#define QS_STR 68
#define KS_STR 68
#define VS_STR 72
#define QS_OFF 0
#define KS_OFF (BQ*QS_STR)
#define VS_OFF (KS_OFF + 2*64*KS_STR)
#define FLASH_SMEM_WORDS (VS_OFF + 2*64*VS_STR)
#define FLASH_SMEM_BYTES (FLASH_SMEM_WORDS * 4)   // 106496

__global__ __launch_bounds__(256, 2) void flash_tf32(
    const float* __restrict__ Q, const float* __restrict__ K,
    const float* __restrict__ V, float* __restrict__ Out)
{
    extern __shared__ uint32_t sm4[];
    uint32_t* Qs = sm4 + QS_OFF;

    const int bh = blockIdx.y;
    const int q0 = blockIdx.x * BQ;
    const int tid  = threadIdx.x;
    const int warp = tid >> 5;
    const int lane = tid & 31;
    const int g = lane >> 2, t = lane & 3;
    const int base = warp * 16;
    const int srcA = (lane & 28) | ((lane & 3) >> 1);
    const int srcB = srcA + 2;
    const bool odd = (t & 1);

    const float* Qg = Q + ((size_t)bh * SEQ + q0) * 64;
    const float* Kg = K + (size_t)bh * SEQ * 64;
    const float* Vg = V + (size_t)bh * SEQ * 64;

    // prologue: stage Q (128x64) and KV tiles 0,1
    #pragma unroll
    for (int j = 0; j < 8; j++) {
        int f = j * 256 + tid;              // 0..2047
        int r = f >> 4, d4 = (f & 15) << 2;
        cp_async16(&Qs[r * QS_STR + d4], Qg + f * 4);
    }
    {
        uint32_t* Kb = sm4 + KS_OFF;
        uint32_t* Vb = sm4 + VS_OFF;
        #pragma unroll
        for (int j = 0; j < 4; j++) {
            int f = j * 256 + tid;          // 0..1023
            int r = f >> 4, d4 = (f & 15) << 2;
            cp_async16(&Kb[r * KS_STR + d4], Kg + f * 4);
            cp_async16(&Vb[r * VS_STR + d4], Vg + f * 4);
        }
    }
    cp_commit();
    {
        uint32_t* Kb = sm4 + KS_OFF + 64 * KS_STR;
        uint32_t* Vb = sm4 + VS_OFF + 64 * VS_STR;
        #pragma unroll
        for (int j = 0; j < 4; j++) {
            int f = j * 256 + tid;
            int r = f >> 4, d4 = (f & 15) << 2;
            cp_async16(&Kb[r * KS_STR + d4], Kg + 64 * 64 + f * 4);
            cp_async16(&Vb[r * VS_STR + d4], Vg + 64 * 64 + f * 4);
        }
    }
    cp_commit();

    float o[8][4];
    float mstate[2], lstate[2];
    mstate[0] = -INFINITY; mstate[1] = -INFINITY;
    lstate[0] = 0.f;       lstate[1] = 0.f;
    #pragma unroll
    for (int nt = 0; nt < 8; nt++)
        #pragma unroll
        for (int j = 0; j < 4; j++) o[nt][j] = 0.f;

    const int NIT = SEQ / 64;
    for (int it = 0; it < NIT; it++) {
        const int buf = it & 1;
        uint32_t* Ks = sm4 + KS_OFF + buf * 64 * KS_STR;
        uint32_t* Vs = sm4 + VS_OFF + buf * 64 * VS_STR;

        cp_wait1();
        __syncthreads();

        // ---- S = Q K^T (log2-scaled) ----
        float sacc[8][4];
        #pragma unroll
        for (int nt = 0; nt < 8; nt++)
            #pragma unroll
            for (int j = 0; j < 4; j++) sacc[nt][j] = 0.f;

        #pragma unroll
        for (int ks = 0; ks < 8; ks++) {
            const int ko = ks * 8 + t;
            uint32_t a[4];
            const int r = base + g;
            a[0] = Qs[r * QS_STR + ko];
            a[1] = Qs[(r + 8) * QS_STR + ko];
            a[2] = Qs[r * QS_STR + ko + 4];
            a[3] = Qs[(r + 8) * QS_STR + ko + 4];
            #pragma unroll
            for (int nt = 0; nt < 8; nt++) {
                const int kr = nt * 8 + g;
                uint32_t b0 = Ks[kr * KS_STR + ko];
                uint32_t b1 = Ks[kr * KS_STR + ko + 4];
                mma8(sacc[nt], a, b0, b1);
            }
        }

        // ---- online softmax (exp2 domain), p in registers ----
        #pragma unroll
        for (int h = 0; h < 2; h++) {
            float mx = -INFINITY;
            #pragma unroll
            for (int nt = 0; nt < 8; nt++)
                mx = fmaxf(mx, fmaxf(sacc[nt][2 * h], sacc[nt][2 * h + 1]));
            mx = fmaxf(mx, __shfl_xor_sync(0xffffffffu, mx, 1));
            mx = fmaxf(mx, __shfl_xor_sync(0xffffffffu, mx, 2));
            float mn = fmaxf(mstate[h], mx);
            float alpha = ex2f(mstate[h] - mn);
            float sum = 0.f;
            #pragma unroll
            for (int nt = 0; nt < 8; nt++) {
                float p0 = tf32f(ex2f(sacc[nt][2 * h] - mn));
                float p1 = tf32f(ex2f(sacc[nt][2 * h + 1] - mn));
                sacc[nt][2 * h]     = p0;
                sacc[nt][2 * h + 1] = p1;
                sum += p0 + p1;
            }
            sum += __shfl_xor_sync(0xffffffffu, sum, 1);
            sum += __shfl_xor_sync(0xffffffffu, sum, 2);
            lstate[h] = lstate[h] * alpha + sum;
            mstate[h] = mn;
            #pragma unroll
            for (int nt = 0; nt < 8; nt++) {
                o[nt][2 * h]     *= alpha;
                o[nt][2 * h + 1] *= alpha;
            }
        }

        // ---- O += P V ----
        #pragma unroll
        for (int ks = 0; ks < 8; ks++) {
            uint32_t a[4];
            pfrag(sacc[ks], srcA, srcB, odd, a);
            #pragma unroll
            for (int nt = 0; nt < 8; nt++) {
                uint32_t b0 = Vs[(ks * 8 + t) * VS_STR + nt * 8 + g];
                uint32_t b1 = Vs[(ks * 8 + t + 4) * VS_STR + nt * 8 + g];
                mma8(o[nt], a, b0, b1);
            }
        }

        __syncthreads();

        if (it + 2 < NIT) {
            uint32_t* Kn = sm4 + KS_OFF + buf * 64 * KS_STR;
            uint32_t* Vn = sm4 + VS_OFF + buf * 64 * VS_STR;
            const float* Kp = Kg + (size_t)(it + 2) * 64 * 64;
            const float* Vp = Vg + (size_t)(it + 2) * 64 * 64;
            #pragma unroll
            for (int j = 0; j < 4; j++) {
                int f = j * 256 + tid;
                int r = f >> 4, d4 = (f & 15) << 2;
                cp_async16(&Kn[r * KS_STR + d4], Kp + f * 4);
                cp_async16(&Vn[r * VS_STR + d4], Vp + f * 4);
            }
        }
        cp_commit();
    }

    // epilogue: normalize, round to tf32, write [b, n, h*64+d]
    const int b = bh / NHEAD, hh = bh % NHEAD;
    #pragma unroll
    for (int h = 0; h < 2; h++) {
        const float inv = 1.0f / lstate[h];
        const int n = q0 + base + g + 8 * h;
        float* orow = Out + ((size_t)(b * SEQ + n)) * CDIM + hh * 64;
        #pragma unroll
        for (int nt = 0; nt < 8; nt++) {
            float2 v = { tf32f(o[nt][2 * h] * inv), tf32f(o[nt][2 * h + 1] * inv) };
            *reinterpret_cast<float2*>(orow + nt * 8 + 2 * t) = v;
        }
    }
}

// ------------------------------- launcher -------------------------------------
extern "C" void kernel_launch(void* const* d_in, const int* in_sizes, int n_in,
                              void* d_out, int out_size)
{
    const float* x        = (const float*)d_in[0];
    const float* rope_cos = (const float*)d_in[1];
    const float* rope_sin = (const float*)d_in[2];
    const float* qkv_k    = (const float*)d_in[3];
    const float* qkv_b    = (const float*)d_in[4];
    const float* proj_k   = (const float*)d_in[5];
    const float* proj_b   = (const float*)d_in[6];
    const float* qw       = (const float*)d_in[7];
    const float* kw       = (const float*)d_in[8];
    float* out = (float*)d_out;

    float *p_qkv, *p_q, *p_k, *p_v, *p_attn, *p_xr, *p_wqr, *p_wpr;
    cudaGetSymbolAddress((void**)&p_qkv,  g_qkv);
    cudaGetSymbolAddress((void**)&p_q,    g_q);
    cudaGetSymbolAddress((void**)&p_k,    g_k);
    cudaGetSymbolAddress((void**)&p_v,    g_v);
    cudaGetSymbolAddress((void**)&p_attn, g_attn);
    cudaGetSymbolAddress((void**)&p_xr,   g_xr);
    cudaGetSymbolAddress((void**)&p_wqr,  g_wqr);
    cudaGetSymbolAddress((void**)&p_wpr,  g_wpr);

    cudaFuncSetAttribute(sgemm_tf32, cudaFuncAttributeMaxDynamicSharedMemorySize, SG_SMEM);
    cudaFuncSetAttribute(flash_tf32, cudaFuncAttributeMaxDynamicSharedMemorySize,
                         FLASH_SMEM_BYTES);

    // 0) pre-round inputs to tf32
    round_tf32<<<(MROWS * CDIM / 4 + 255) / 256, 256>>>(x, p_xr, MROWS * CDIM / 4);
    round_tf32<<<(CDIM * QKVN / 4 + 255) / 256, 256>>>(qkv_k, p_wqr, CDIM * QKVN / 4);
    round_tf32<<<(CDIM * CDIM / 4 + 255) / 256, 256>>>(proj_k, p_wpr, CDIM * CDIM / 4);

    // 1) QKV GEMM
    {
        dim3 grid(QKVN / 128, MROWS / 128);
        sgemm_tf32<<<grid, 256, SG_SMEM>>>(MROWS, QKVN, CDIM, p_xr, p_wqr, qkv_b, p_qkv);
    }

    // 2) RMSNorm + RoPE + scatter
    {
        int warps = BATCH * SEQ * NHEAD;
        int blocks = (warps * 32 + 255) / 256;
        qkv_post<<<blocks, 256>>>(p_qkv, rope_cos, rope_sin, qw, kw, p_q, p_k, p_v);
    }

    // 3) flash attention (8 warps x 16 rows, 2 CTAs/SM)
    {
        dim3 grid(SEQ / BQ, BHTOT);
        flash_tf32<<<grid, 256, FLASH_SMEM_BYTES>>>(p_q, p_k, p_v, p_attn);
    }

    // 4) projection GEMM
    {
        dim3 grid(CDIM / 128, MROWS / 128);
        sgemm_tf32<<<grid, 256, SG_SMEM>>>(MROWS, CDIM, CDIM, p_attn, p_wpr, proj_b, out);
    }
}

// round 11
// speedup vs baseline: 1.5785x; 1.5785x over previous
#include <cuda_runtime.h>
#include <cuda_bf16.h>
#include <stdint.h>
#include <math.h>

// Problem constants
#define BATCH 2
#define SEQ   2048
#define CDIM  768
#define NHEAD 12
#define HDIM  64
#define BHTOT (BATCH*NHEAD)          // 24
#define MROWS (BATCH*SEQ)            // 4096
#define QKVN  (3*CDIM)               // 2304

// ---------------- scratch (device globals; no allocation allowed) -------------
__device__ float g_qkv[(size_t)MROWS * QKVN];
__device__ float g_q[(size_t)BHTOT * SEQ * HDIM];
__device__ float g_k[(size_t)BHTOT * SEQ * HDIM];
__device__ float g_v[(size_t)BHTOT * SEQ * HDIM];
__device__ float g_attn[(size_t)MROWS * CDIM];
__device__ float g_xr[(size_t)MROWS * CDIM];
__device__ float g_wqr[(size_t)CDIM * QKVN];
__device__ float g_wpr[(size_t)CDIM * CDIM];

// ---------------- helpers ------------------------------------------------------
__device__ __forceinline__ uint32_t tf32r(float f) {
    uint32_t u; asm("cvt.rna.tf32.f32 %0, %1;" : "=r"(u) : "f"(f)); return u;
}
__device__ __forceinline__ float tf32f(float f) { return __uint_as_float(tf32r(f)); }
__device__ __forceinline__ float ex2f(float x) {
    float y; asm("ex2.approx.f32 %0, %1;" : "=f"(y) : "f"(x)); return y;
}
__device__ __forceinline__ void mma8(float* c, const uint32_t* a, uint32_t b0, uint32_t b1) {
    asm volatile(
        "mma.sync.aligned.m16n8k8.row.col.f32.tf32.tf32.f32 "
        "{%0,%1,%2,%3}, {%4,%5,%6,%7}, {%8,%9}, {%0,%1,%2,%3};\n"
        : "+f"(c[0]), "+f"(c[1]), "+f"(c[2]), "+f"(c[3])
        : "r"(a[0]), "r"(a[1]), "r"(a[2]), "r"(a[3]), "r"(b0), "r"(b1));
}
__device__ __forceinline__ void cp_async16(void* dst_smem, const void* src_gmem) {
    uint32_t d = (uint32_t)__cvta_generic_to_shared(dst_smem);
    asm volatile("cp.async.cg.shared.global [%0], [%1], 16;\n" :: "r"(d), "l"(src_gmem));
}
__device__ __forceinline__ void cp_commit() { asm volatile("cp.async.commit_group;\n"); }
__device__ __forceinline__ void cp_wait1()  { asm volatile("cp.async.wait_group 1;\n"); }

__device__ __forceinline__ void pfrag(const float* c, int srcA, int srcB, bool odd,
                                      uint32_t* a) {
    float v00 = __shfl_sync(0xffffffffu, c[0], srcA);
    float v01 = __shfl_sync(0xffffffffu, c[1], srcA);
    float v10 = __shfl_sync(0xffffffffu, c[2], srcA);
    float v11 = __shfl_sync(0xffffffffu, c[3], srcA);
    float w00 = __shfl_sync(0xffffffffu, c[0], srcB);
    float w01 = __shfl_sync(0xffffffffu, c[1], srcB);
    float w10 = __shfl_sync(0xffffffffu, c[2], srcB);
    float w11 = __shfl_sync(0xffffffffu, c[3], srcB);
    a[0] = __float_as_uint(odd ? v01 : v00);
    a[1] = __float_as_uint(odd ? v11 : v10);
    a[2] = __float_as_uint(odd ? w01 : w00);
    a[3] = __float_as_uint(odd ? w11 : w10);
}

// ---------------- prep: round fp32 -> tf32 bits in gmem -------------------------
__global__ __launch_bounds__(256) void round_tf32(
    const float* __restrict__ src, float* __restrict__ dst, int n4)
{
    int i = blockIdx.x * blockDim.x + threadIdx.x;
    if (i >= n4) return;
    float4 v = *reinterpret_cast<const float4*>(src + (size_t)i * 4);
    v.x = tf32f(v.x); v.y = tf32f(v.y); v.z = tf32f(v.z); v.w = tf32f(v.w);
    *reinterpret_cast<float4*>(dst + (size_t)i * 4) = v;
}

// ---------------- TF32 tensor-core SGEMM + bias (BK=32, 3-stage cp.async) -------
#define AS_STR 36
#define BS_STR 136
#define STAGE_WORDS (128*AS_STR + 32*BS_STR)   // 8960
#define SG_SMEM (3*STAGE_WORDS*4)              // 107520 B

__global__ __launch_bounds__(256) void sgemm_tf32(
    int M, int N, int K,
    const float* __restrict__ A, const float* __restrict__ B,
    const float* __restrict__ bias, float* __restrict__ C)
{
    extern __shared__ uint32_t smw[];

    const int tid  = threadIdx.x;
    const int warp = tid >> 5;
    const int lane = tid & 31;
    const int g = lane >> 2, t = lane & 3;
    const int warp_m = warp >> 2;
    const int warp_n = warp & 3;
    const int brow = blockIdx.y, bcol = blockIdx.x;

    const float* Ablk = A + (size_t)brow * 128 * K;
    const float* Bblk = B + (size_t)bcol * 128;
    const int ktiles = K >> 5;

    float acc[4][4][4];
    #pragma unroll
    for (int mt = 0; mt < 4; mt++)
        #pragma unroll
        for (int nt = 0; nt < 4; nt++)
            #pragma unroll
            for (int j = 0; j < 4; j++) acc[mt][nt][j] = 0.f;

    auto stage = [&](int kt, int s) {
        uint32_t* As = smw + s * STAGE_WORDS;
        uint32_t* Bs = As + 128 * AS_STR;
        #pragma unroll
        for (int j = 0; j < 4; j++) {
            int f = j * 256 + tid;
            int r = f >> 3, c4 = (f & 7) << 2;
            cp_async16(&As[r * AS_STR + c4], Ablk + (size_t)r * K + kt * 32 + c4);
        }
        #pragma unroll
        for (int j = 0; j < 4; j++) {
            int f = j * 256 + tid;
            int kr = f >> 5, n4 = (f & 31) << 2;
            cp_async16(&Bs[kr * BS_STR + n4], Bblk + (size_t)(kt * 32 + kr) * N + n4);
        }
    };

    stage(0, 0); cp_commit();
    stage(1, 1); cp_commit();

    for (int kt = 0; kt < ktiles; kt++) {
        cp_wait1();
        __syncthreads();
        if (kt + 2 < ktiles) stage(kt + 2, (kt + 2) % 3);
        cp_commit();

        const uint32_t* As = smw + (kt % 3) * STAGE_WORDS;
        const uint32_t* Bs = As + 128 * AS_STR;

        #pragma unroll
        for (int s = 0; s < 4; s++) {
            const int ko = s * 8;
            uint32_t a[4][4], bf[4][2];
            #pragma unroll
            for (int mt = 0; mt < 4; mt++) {
                const int r = warp_m * 64 + mt * 16 + g;
                a[mt][0] = As[r * AS_STR + ko + t];
                a[mt][1] = As[(r + 8) * AS_STR + ko + t];
                a[mt][2] = As[r * AS_STR + ko + t + 4];
                a[mt][3] = As[(r + 8) * AS_STR + ko + t + 4];
            }
            #pragma unroll
            for (int nt = 0; nt < 4; nt++) {
                const int c = warp_n * 32 + nt * 8 + g;
                bf[nt][0] = Bs[(ko + t) * BS_STR + c];
                bf[nt][1] = Bs[(ko + t + 4) * BS_STR + c];
            }
            #pragma unroll
            for (int mt = 0; mt < 4; mt++)
                #pragma unroll
                for (int nt = 0; nt < 4; nt++)
                    mma8(acc[mt][nt], a[mt], bf[nt][0], bf[nt][1]);
        }
    }

    #pragma unroll
    for (int mt = 0; mt < 4; mt++) {
        const int r0 = brow * 128 + warp_m * 64 + mt * 16 + g;
        #pragma unroll
        for (int nt = 0; nt < 4; nt++) {
            const int c = bcol * 128 + warp_n * 32 + nt * 8 + 2 * t;
            float b0 = bias[c], b1 = bias[c + 1];
            float2 v0 = { acc[mt][nt][0] + b0, acc[mt][nt][1] + b1 };
            float2 v1 = { acc[mt][nt][2] + b0, acc[mt][nt][3] + b1 };
            *reinterpret_cast<float2*>(C + (size_t)r0 * N + c) = v0;
            *reinterpret_cast<float2*>(C + (size_t)(r0 + 8) * N + c) = v1;
        }
    }
}

// --------- QKV post: RMSNorm(q,k) + RoPE(q,k) + scale(q), scatter, tf32-round --
__global__ __launch_bounds__(256) void qkv_post(
    const float* __restrict__ qkv,
    const float* __restrict__ cosb, const float* __restrict__ sinb,
    const float* __restrict__ qw,   const float* __restrict__ kw,
    float* __restrict__ Q, float* __restrict__ K, float* __restrict__ V)
{
    int warp = (blockIdx.x * blockDim.x + threadIdx.x) >> 5;
    int lane = threadIdx.x & 31;
    const int NW = BATCH * SEQ * NHEAD;
    if (warp >= NW) return;
    int h = warp % NHEAD;
    int n = (warp / NHEAD) % SEQ;
    int b = warp / (NHEAD * SEQ);

    const float* row = qkv + (size_t)(b * SEQ + n) * QKVN;
    float q0 = row[h * 64 + lane],            q1 = row[h * 64 + lane + 32];
    float k0 = row[CDIM + h * 64 + lane],     k1 = row[CDIM + h * 64 + lane + 32];
    float v0 = row[2 * CDIM + h * 64 + lane], v1 = row[2 * CDIM + h * 64 + lane + 32];

    float sq = q0 * q0 + q1 * q1;
    float sk = k0 * k0 + k1 * k1;
    #pragma unroll
    for (int o = 16; o > 0; o >>= 1) {
        sq += __shfl_xor_sync(0xffffffffu, sq, o);
        sk += __shfl_xor_sync(0xffffffffu, sk, o);
    }
    float rq = rsqrtf(sq * (1.0f / 64.0f) + 1e-6f);
    float rk = rsqrtf(sk * (1.0f / 64.0f) + 1e-6f);
    q0 *= rq * qw[lane]; q1 *= rq * qw[lane + 32];
    k0 *= rk * kw[lane]; k1 *= rk * kw[lane + 32];

    float c0 = cosb[n * 64 + lane], c1 = cosb[n * 64 + lane + 32];
    float s0 = sinb[n * 64 + lane], s1 = sinb[n * 64 + lane + 32];
    float qr0 = q0 * c0 - q1 * s0;
    float qr1 = q1 * c1 + q0 * s1;
    float kr0 = k0 * c0 - k1 * s0;
    float kr1 = k1 * c1 + k0 * s1;

    const float scale = 0.125f * 1.4426950408889634f;
    int bh = b * NHEAD + h;
    float* qo = Q + ((size_t)bh * SEQ + n) * 64;
    float* ko = K + ((size_t)bh * SEQ + n) * 64;
    float* vo = V + ((size_t)bh * SEQ + n) * 64;
    qo[lane] = tf32f(qr0 * scale); qo[lane + 32] = tf32f(qr1 * scale);
    ko[lane] = tf32f(kr0);         ko[lane + 32] = tf32f(kr1);
    vo[lane] = tf32f(v0);          vo[lane + 32] = tf32f(v1);
}

// ---------------- TF32 flash attention (R8-proven: 4 warps x 32 rows) -----------
#define BQ 128
#define QS_STR 68
#define KS_STR 68
#define VS_STR 72
#define QS_OFF 0
#define KS_OFF (BQ*QS_STR)
#define VS_OFF (KS_OFF + 2*64*KS_STR)
#define FLASH_SMEM_WORDS (VS_OFF + 2*64*VS_STR)
#define FLASH_SMEM_BYTES (FLASH_SMEM_WORDS * 4)   // 106496

__global__ __launch_bounds__(128, 2) void flash_tf32(
    const float* __restrict__ Q, const float* __restrict__ K,
    const float* __restrict__ V, float* __restrict__ Out)
{
    extern __shared__ uint32_t sm4[];
    uint32_t* Qs = sm4 + QS_OFF;

    const int bh = blockIdx.y;
    const int q0 = blockIdx.x * BQ;
    const int tid  = threadIdx.x;
    const int warp = tid >> 5;
    const int lane = tid & 31;
    const int g = lane >> 2, t = lane & 3;
    const int base = warp * 32;
    const int srcA = (lane & 28) | ((lane & 3) >> 1);
    const int srcB = srcA + 2;
    const bool odd = (t & 1);

    const float* Qg = Q + ((size_t)bh * SEQ + q0) * 64;
    const float* Kg = K + (size_t)bh * SEQ * 64;
    const float* Vg = V + (size_t)bh * SEQ * 64;

    #pragma unroll
    for (int j = 0; j < 16; j++) {
        int f = j * 128 + tid;
        int r = f >> 4, d4 = (f & 15) << 2;
        cp_async16(&Qs[r * QS_STR + d4], Qg + f * 4);
    }
    {
        uint32_t* Kb = sm4 + KS_OFF;
        uint32_t* Vb = sm4 + VS_OFF;
        #pragma unroll
        for (int j = 0; j < 8; j++) {
            int f = j * 128 + tid;
            int r = f >> 4, d4 = (f & 15) << 2;
            cp_async16(&Kb[r * KS_STR + d4], Kg + f * 4);
            cp_async16(&Vb[r * VS_STR + d4], Vg + f * 4);
        }
    }
    cp_commit();
    {
        uint32_t* Kb = sm4 + KS_OFF + 64 * KS_STR;
        uint32_t* Vb = sm4 + VS_OFF + 64 * VS_STR;
        #pragma unroll
        for (int j = 0; j < 8; j++) {
            int f = j * 128 + tid;
            int r = f >> 4, d4 = (f & 15) << 2;
            cp_async16(&Kb[r * KS_STR + d4], Kg + 64 * 64 + f * 4);
            cp_async16(&Vb[r * VS_STR + d4], Vg + 64 * 64 + f * 4);
        }
    }
    cp_commit();

    float o[2][8][4];
    float mstate[2][2], lstate[2][2];
    #pragma unroll
    for (int mt = 0; mt < 2; mt++) {
        mstate[mt][0] = -INFINITY; mstate[mt][1] = -INFINITY;
        lstate[mt][0] = 0.f;       lstate[mt][1] = 0.f;
        #pragma unroll
        for (int nt = 0; nt < 8; nt++)
            #pragma unroll
            for (int j = 0; j < 4; j++) o[mt][nt][j] = 0.f;
    }

    const int NIT = SEQ / 64;
    #pragma unroll 2
    for (int it = 0; it < NIT; it++) {
        const int buf = it & 1;
        uint32_t* Ks = sm4 + KS_OFF + buf * 64 * KS_STR;
        uint32_t* Vs = sm4 + VS_OFF + buf * 64 * VS_STR;

        cp_wait1();
        __syncthreads();

        float sacc[2][8][4];
        #pragma unroll
        for (int mt = 0; mt < 2; mt++)
            #pragma unroll
            for (int nt = 0; nt < 8; nt++)
                #pragma unroll
                for (int j = 0; j < 4; j++) sacc[mt][nt][j] = 0.f;

        #pragma unroll
        for (int ks = 0; ks < 8; ks++) {
            const int ko = ks * 8 + t;
            uint32_t a[2][4];
            #pragma unroll
            for (int mt = 0; mt < 2; mt++) {
                const int r = base + mt * 16 + g;
                a[mt][0] = Qs[r * QS_STR + ko];
                a[mt][1] = Qs[(r + 8) * QS_STR + ko];
                a[mt][2] = Qs[r * QS_STR + ko + 4];
                a[mt][3] = Qs[(r + 8) * QS_STR + ko + 4];
            }
            #pragma unroll
            for (int nt = 0; nt < 8; nt++) {
                const int kr = nt * 8 + g;
                uint32_t b0 = Ks[kr * KS_STR + ko];
                uint32_t b1 = Ks[kr * KS_STR + ko + 4];
                mma8(sacc[0][nt], a[0], b0, b1);
                mma8(sacc[1][nt], a[1], b0, b1);
            }
        }

        #pragma unroll
        for (int mt = 0; mt < 2; mt++) {
            #pragma unroll
            for (int h = 0; h < 2; h++) {
                float mx = -INFINITY;
                #pragma unroll
                for (int nt = 0; nt < 8; nt++)
                    mx = fmaxf(mx, fmaxf(sacc[mt][nt][2 * h], sacc[mt][nt][2 * h + 1]));
                mx = fmaxf(mx, __shfl_xor_sync(0xffffffffu, mx, 1));
                mx = fmaxf(mx, __shfl_xor_sync(0xffffffffu, mx, 2));
                float mn = fmaxf(mstate[mt][h], mx);
                float alpha = ex2f(mstate[mt][h] - mn);
                float sum = 0.f;
                #pragma unroll
                for (int nt = 0; nt < 8; nt++) {
                    float p0 = tf32f(ex2f(sacc[mt][nt][2 * h] - mn));
                    float p1 = tf32f(ex2f(sacc[mt][nt][2 * h + 1] - mn));
                    sacc[mt][nt][2 * h]     = p0;
                    sacc[mt][nt][2 * h + 1] = p1;
                    sum += p0 + p1;
                }
                sum += __shfl_xor_sync(0xffffffffu, sum, 1);
                sum += __shfl_xor_sync(0xffffffffu, sum, 2);
                lstate[mt][h] = lstate[mt][h] * alpha + sum;
                mstate[mt][h] = mn;
                #pragma unroll
                for (int nt = 0; nt < 8; nt++) {
                    o[mt][nt][2 * h]     *= alpha;
                    o[mt][nt][2 * h + 1] *= alpha;
                }
            }
        }

        #pragma unroll
        for (int ks = 0; ks < 8; ks++) {
            uint32_t a0[4], a1[4];
            pfrag(sacc[0][ks], srcA, srcB, odd, a0);
            pfrag(sacc[1][ks], srcA, srcB, odd, a1);
            #pragma unroll
            for (int nt = 0; nt < 8; nt++) {
                uint32_t b0 = Vs[(ks * 8 + t) * VS_STR + nt * 8 + g];
                uint32_t b1 = Vs[(ks * 8 + t + 4) * VS_STR + nt * 8 + g];
                mma8(o[0][nt], a0, b0, b1);
                mma8(o[1][nt], a1, b0, b1);
            }
        }

        __syncthreads();

        if (it + 2 < NIT) {
            uint32_t* Kn = sm4 + KS_OFF + buf * 64 * KS_STR;
            uint32_t* Vn = sm4 + VS_OFF + buf * 64 * VS_STR;
            const float* Kp = Kg + (size_t)(it + 2) * 64 * 64;
            const float* Vp = Vg + (size_t)(it + 2) * 64 * 64;
            #pragma unroll
            for (int j = 0; j < 8; j++) {
                int f = j * 128 + tid;
                int r = f >> 4, d4 = (f & 15) << 2;
                cp_async16(&Kn[r * KS_STR + d4], Kp + f * 4);
                cp_async16(&Vn[r * VS_STR + d4], Vp + f * 4);
            }
        }
        cp_commit();
    }

    // epilogue: normalize, round to tf32 (proj GEMM input), write [b, n, h*64+d]
    const int b = bh / NHEAD, hh = bh % NHEAD;
    #pragma unroll
    for (int mt = 0; mt < 2; mt++) {
        #pragma unroll
        for (int h = 0; h < 2; h++) {
            const float inv = 1.0f / lstate[mt][h];
            const int n = q0 + base + mt * 16 + g + 8 * h;
            float* orow = Out + ((size_t)(b * SEQ + n)) * CDIM + hh * 64;
            #pragma unroll
            for (int nt = 0; nt < 8; nt++) {
                float2 v = { tf32f(o[mt][nt][2 * h] * inv),
                             tf32f(o[mt][nt][2 * h + 1] * inv) };
                *reinterpret_cast<float2*>(orow + nt * 8 + 2 * t) = v;
            }
        }
    }
}

// ------------------------------- launcher -------------------------------------
extern "C" void kernel_launch(void* const* d_in, const int* in_sizes, int n_in,
                              void* d_out, int out_size)
{
    const float* x        = (const float*)d_in[0];
    const float* rope_cos = (const float*)d_in[1];
    const float* rope_sin = (const float*)d_in[2];
    const float* qkv_k    = (const float*)d_in[3];
    const float* qkv_b    = (const float*)d_in[4];
    const float* proj_k   = (const float*)d_in[5];
    const float* proj_b   = (const float*)d_in[6];
    const float* qw       = (const float*)d_in[7];
    const float* kw       = (const float*)d_in[8];
    float* out = (float*)d_out;

    float *p_qkv, *p_q, *p_k, *p_v, *p_attn, *p_xr, *p_wqr, *p_wpr;
    cudaGetSymbolAddress((void**)&p_qkv,  g_qkv);
    cudaGetSymbolAddress((void**)&p_q,    g_q);
    cudaGetSymbolAddress((void**)&p_k,    g_k);
    cudaGetSymbolAddress((void**)&p_v,    g_v);
    cudaGetSymbolAddress((void**)&p_attn, g_attn);
    cudaGetSymbolAddress((void**)&p_xr,   g_xr);
    cudaGetSymbolAddress((void**)&p_wqr,  g_wqr);
    cudaGetSymbolAddress((void**)&p_wpr,  g_wpr);

    cudaFuncSetAttribute(sgemm_tf32, cudaFuncAttributeMaxDynamicSharedMemorySize, SG_SMEM);
    cudaFuncSetAttribute(flash_tf32, cudaFuncAttributeMaxDynamicSharedMemorySize,
                         FLASH_SMEM_BYTES);

    // 0) pre-round inputs to tf32
    round_tf32<<<(MROWS * CDIM / 4 + 255) / 256, 256>>>(x, p_xr, MROWS * CDIM / 4);
    round_tf32<<<(CDIM * QKVN / 4 + 255) / 256, 256>>>(qkv_k, p_wqr, CDIM * QKVN / 4);
    round_tf32<<<(CDIM * CDIM / 4 + 255) / 256, 256>>>(proj_k, p_wpr, CDIM * CDIM / 4);

    // 1) QKV GEMM
    {
        dim3 grid(QKVN / 128, MROWS / 128);
        sgemm_tf32<<<grid, 256, SG_SMEM>>>(MROWS, QKVN, CDIM, p_xr, p_wqr, qkv_b, p_qkv);
    }

    // 2) RMSNorm + RoPE + scatter
    {
        int warps = BATCH * SEQ * NHEAD;
        int blocks = (warps * 32 + 255) / 256;
        qkv_post<<<blocks, 256>>>(p_qkv, rope_cos, rope_sin, qw, kw, p_q, p_k, p_v);
    }

    // 3) flash attention (4 warps x 32 rows, 2 CTAs/SM — R8 config)
    {
        dim3 grid(SEQ / BQ, BHTOT);
        flash_tf32<<<grid, 128, FLASH_SMEM_BYTES>>>(p_q, p_k, p_v, p_attn);
    }

    // 4) projection GEMM
    {
        dim3 grid(CDIM / 128, MROWS / 128);
        sgemm_tf32<<<grid, 256, SG_SMEM>>>(MROWS, CDIM, CDIM, p_attn, p_wpr, proj_b, out);
    }
}

// round 12
// speedup vs baseline: 1.6271x; 1.0308x over previous
#include <cuda_runtime.h>
#include <cuda_bf16.h>
#include <stdint.h>
#include <math.h>

// Problem constants
#define BATCH 2
#define SEQ   2048
#define CDIM  768
#define NHEAD 12
#define HDIM  64
#define BHTOT (BATCH*NHEAD)          // 24
#define MROWS (BATCH*SEQ)            // 4096
#define QKVN  (3*CDIM)               // 2304

// ---------------- scratch (device globals; no allocation allowed) -------------
__device__ float g_qkv[(size_t)MROWS * QKVN];
__device__ float g_q[(size_t)BHTOT * SEQ * HDIM];
__device__ float g_k[(size_t)BHTOT * SEQ * HDIM];
__device__ float g_v[(size_t)BHTOT * SEQ * HDIM];
__device__ float g_attn[(size_t)MROWS * CDIM];
__device__ float g_xr[(size_t)MROWS * CDIM];
__device__ float g_wqr[(size_t)CDIM * QKVN];
__device__ float g_wpr[(size_t)CDIM * CDIM];

// ---------------- helpers ------------------------------------------------------
__device__ __forceinline__ uint32_t tf32r(float f) {
    uint32_t u; asm("cvt.rna.tf32.f32 %0, %1;" : "=r"(u) : "f"(f)); return u;
}
__device__ __forceinline__ float tf32f(float f) { return __uint_as_float(tf32r(f)); }
__device__ __forceinline__ float ex2f(float x) {
    float y; asm("ex2.approx.f32 %0, %1;" : "=f"(y) : "f"(x)); return y;
}
__device__ __forceinline__ void mma8(float* c, const uint32_t* a, uint32_t b0, uint32_t b1) {
    asm volatile(
        "mma.sync.aligned.m16n8k8.row.col.f32.tf32.tf32.f32 "
        "{%0,%1,%2,%3}, {%4,%5,%6,%7}, {%8,%9}, {%0,%1,%2,%3};\n"
        : "+f"(c[0]), "+f"(c[1]), "+f"(c[2]), "+f"(c[3])
        : "r"(a[0]), "r"(a[1]), "r"(a[2]), "r"(a[3]), "r"(b0), "r"(b1));
}
__device__ __forceinline__ void cp_async16(void* dst_smem, const void* src_gmem) {
    uint32_t d = (uint32_t)__cvta_generic_to_shared(dst_smem);
    asm volatile("cp.async.cg.shared.global [%0], [%1], 16;\n" :: "r"(d), "l"(src_gmem));
}
__device__ __forceinline__ void cp_commit() { asm volatile("cp.async.commit_group;\n"); }
__device__ __forceinline__ void cp_wait1()  { asm volatile("cp.async.wait_group 1;\n"); }

__device__ __forceinline__ void pfrag(const float* c, int srcA, int srcB, bool odd,
                                      uint32_t* a) {
    float v00 = __shfl_sync(0xffffffffu, c[0], srcA);
    float v01 = __shfl_sync(0xffffffffu, c[1], srcA);
    float v10 = __shfl_sync(0xffffffffu, c[2], srcA);
    float v11 = __shfl_sync(0xffffffffu, c[3], srcA);
    float w00 = __shfl_sync(0xffffffffu, c[0], srcB);
    float w01 = __shfl_sync(0xffffffffu, c[1], srcB);
    float w10 = __shfl_sync(0xffffffffu, c[2], srcB);
    float w11 = __shfl_sync(0xffffffffu, c[3], srcB);
    a[0] = __float_as_uint(odd ? v01 : v00);
    a[1] = __float_as_uint(odd ? v11 : v10);
    a[2] = __float_as_uint(odd ? w01 : w00);
    a[3] = __float_as_uint(odd ? w11 : w10);
}

// ---------------- prep: round fp32 -> tf32 bits in gmem -------------------------
__global__ __launch_bounds__(256) void round_tf32(
    const float* __restrict__ src, float* __restrict__ dst, int n4)
{
    int i = blockIdx.x * blockDim.x + threadIdx.x;
    if (i >= n4) return;
    float4 v = *reinterpret_cast<const float4*>(src + (size_t)i * 4);
    v.x = tf32f(v.x); v.y = tf32f(v.y); v.z = tf32f(v.z); v.w = tf32f(v.w);
    *reinterpret_cast<float4*>(dst + (size_t)i * 4) = v;
}

// ---------------- TF32 tensor-core SGEMM + bias (BK=32, 3-stage, 2 CTAs/SM) -----
#define AS_STR 36
#define BS_STR 136
#define STAGE_WORDS (128*AS_STR + 32*BS_STR)   // 8960
#define SG_SMEM (3*STAGE_WORDS*4)              // 107520 B

__global__ __launch_bounds__(256, 2) void sgemm_tf32(
    int M, int N, int K,
    const float* __restrict__ A, const float* __restrict__ B,
    const float* __restrict__ bias, float* __restrict__ C)
{
    extern __shared__ uint32_t smw[];

    const int tid  = threadIdx.x;
    const int warp = tid >> 5;
    const int lane = tid & 31;
    const int g = lane >> 2, t = lane & 3;
    const int warp_m = warp >> 2;
    const int warp_n = warp & 3;
    const int brow = blockIdx.y, bcol = blockIdx.x;

    const float* Ablk = A + (size_t)brow * 128 * K;
    const float* Bblk = B + (size_t)bcol * 128;
    const int ktiles = K >> 5;

    float acc[4][4][4];
    #pragma unroll
    for (int mt = 0; mt < 4; mt++)
        #pragma unroll
        for (int nt = 0; nt < 4; nt++)
            #pragma unroll
            for (int j = 0; j < 4; j++) acc[mt][nt][j] = 0.f;

    auto stage = [&](int kt, int s) {
        uint32_t* As = smw + s * STAGE_WORDS;
        uint32_t* Bs = As + 128 * AS_STR;
        #pragma unroll
        for (int j = 0; j < 4; j++) {
            int f = j * 256 + tid;
            int r = f >> 3, c4 = (f & 7) << 2;
            cp_async16(&As[r * AS_STR + c4], Ablk + (size_t)r * K + kt * 32 + c4);
        }
        #pragma unroll
        for (int j = 0; j < 4; j++) {
            int f = j * 256 + tid;
            int kr = f >> 5, n4 = (f & 31) << 2;
            cp_async16(&Bs[kr * BS_STR + n4], Bblk + (size_t)(kt * 32 + kr) * N + n4);
        }
    };

    stage(0, 0); cp_commit();
    stage(1, 1); cp_commit();

    for (int kt = 0; kt < ktiles; kt++) {
        cp_wait1();
        __syncthreads();
        if (kt + 2 < ktiles) stage(kt + 2, (kt + 2) % 3);
        cp_commit();

        const uint32_t* As = smw + (kt % 3) * STAGE_WORDS;
        const uint32_t* Bs = As + 128 * AS_STR;

        #pragma unroll
        for (int s = 0; s < 4; s++) {
            const int ko = s * 8;
            uint32_t a[4][4], bf[4][2];
            #pragma unroll
            for (int mt = 0; mt < 4; mt++) {
                const int r = warp_m * 64 + mt * 16 + g;
                a[mt][0] = As[r * AS_STR + ko + t];
                a[mt][1] = As[(r + 8) * AS_STR + ko + t];
                a[mt][2] = As[r * AS_STR + ko + t + 4];
                a[mt][3] = As[(r + 8) * AS_STR + ko + t + 4];
            }
            #pragma unroll
            for (int nt = 0; nt < 4; nt++) {
                const int c = warp_n * 32 + nt * 8 + g;
                bf[nt][0] = Bs[(ko + t) * BS_STR + c];
                bf[nt][1] = Bs[(ko + t + 4) * BS_STR + c];
            }
            #pragma unroll
            for (int mt = 0; mt < 4; mt++)
                #pragma unroll
                for (int nt = 0; nt < 4; nt++)
                    mma8(acc[mt][nt], a[mt], bf[nt][0], bf[nt][1]);
        }
    }

    #pragma unroll
    for (int mt = 0; mt < 4; mt++) {
        const int r0 = brow * 128 + warp_m * 64 + mt * 16 + g;
        #pragma unroll
        for (int nt = 0; nt < 4; nt++) {
            const int c = bcol * 128 + warp_n * 32 + nt * 8 + 2 * t;
            float b0 = bias[c], b1 = bias[c + 1];
            float2 v0 = { acc[mt][nt][0] + b0, acc[mt][nt][1] + b1 };
            float2 v1 = { acc[mt][nt][2] + b0, acc[mt][nt][3] + b1 };
            *reinterpret_cast<float2*>(C + (size_t)r0 * N + c) = v0;
            *reinterpret_cast<float2*>(C + (size_t)(r0 + 8) * N + c) = v1;
        }
    }
}

// --------- QKV post: RMSNorm(q,k) + RoPE(q,k) + scale(q), scatter, tf32-round --
__global__ __launch_bounds__(256) void qkv_post(
    const float* __restrict__ qkv,
    const float* __restrict__ cosb, const float* __restrict__ sinb,
    const float* __restrict__ qw,   const float* __restrict__ kw,
    float* __restrict__ Q, float* __restrict__ K, float* __restrict__ V)
{
    int warp = (blockIdx.x * blockDim.x + threadIdx.x) >> 5;
    int lane = threadIdx.x & 31;
    const int NW = BATCH * SEQ * NHEAD;
    if (warp >= NW) return;
    int h = warp % NHEAD;
    int n = (warp / NHEAD) % SEQ;
    int b = warp / (NHEAD * SEQ);

    const float* row = qkv + (size_t)(b * SEQ + n) * QKVN;
    float q0 = row[h * 64 + lane],            q1 = row[h * 64 + lane + 32];
    float k0 = row[CDIM + h * 64 + lane],     k1 = row[CDIM + h * 64 + lane + 32];
    float v0 = row[2 * CDIM + h * 64 + lane], v1 = row[2 * CDIM + h * 64 + lane + 32];

    float sq = q0 * q0 + q1 * q1;
    float sk = k0 * k0 + k1 * k1;
    #pragma unroll
    for (int o = 16; o > 0; o >>= 1) {
        sq += __shfl_xor_sync(0xffffffffu, sq, o);
        sk += __shfl_xor_sync(0xffffffffu, sk, o);
    }
    float rq = rsqrtf(sq * (1.0f / 64.0f) + 1e-6f);
    float rk = rsqrtf(sk * (1.0f / 64.0f) + 1e-6f);
    q0 *= rq * qw[lane]; q1 *= rq * qw[lane + 32];
    k0 *= rk * kw[lane]; k1 *= rk * kw[lane + 32];

    float c0 = cosb[n * 64 + lane], c1 = cosb[n * 64 + lane + 32];
    float s0 = sinb[n * 64 + lane], s1 = sinb[n * 64 + lane + 32];
    float qr0 = q0 * c0 - q1 * s0;
    float qr1 = q1 * c1 + q0 * s1;
    float kr0 = k0 * c0 - k1 * s0;
    float kr1 = k1 * c1 + k0 * s1;

    const float scale = 0.125f * 1.4426950408889634f;
    int bh = b * NHEAD + h;
    float* qo = Q + ((size_t)bh * SEQ + n) * 64;
    float* ko = K + ((size_t)bh * SEQ + n) * 64;
    float* vo = V + ((size_t)bh * SEQ + n) * 64;
    qo[lane] = tf32f(qr0 * scale); qo[lane + 32] = tf32f(qr1 * scale);
    ko[lane] = tf32f(kr0);         ko[lane + 32] = tf32f(kr1);
    vo[lane] = tf32f(v0);          vo[lane + 32] = tf32f(v1);
}

// ---------------- TF32 flash attention (R8-proven: 4 warps x 32 rows) -----------
#define BQ 128
#define QS_STR 68
#define KS_STR 68
#define VS_STR 72
#define QS_OFF 0
#define KS_OFF (BQ*QS_STR)
#define VS_OFF (KS_OFF + 2*64*KS_STR)
#define FLASH_SMEM_WORDS (VS_OFF + 2*64*VS_STR)
#define FLASH_SMEM_BYTES (FLASH_SMEM_WORDS * 4)   // 106496

__global__ __launch_bounds__(128, 2) void flash_tf32(
    const float* __restrict__ Q, const float* __restrict__ K,
    const float* __restrict__ V, float* __restrict__ Out)
{
    extern __shared__ uint32_t sm4[];
    uint32_t* Qs = sm4 + QS_OFF;

    const int bh = blockIdx.y;
    const int q0 = blockIdx.x * BQ;
    const int tid  = threadIdx.x;
    const int warp = tid >> 5;
    const int lane = tid & 31;
    const int g = lane >> 2, t = lane & 3;
    const int base = warp * 32;
    const int srcA = (lane & 28) | ((lane & 3) >> 1);
    const int srcB = srcA + 2;
    const bool odd = (t & 1);

    const float* Qg = Q + ((size_t)bh * SEQ + q0) * 64;
    const float* Kg = K + (size_t)bh * SEQ * 64;
    const float* Vg = V + (size_t)bh * SEQ * 64;

    #pragma unroll
    for (int j = 0; j < 16; j++) {
        int f = j * 128 + tid;
        int r = f >> 4, d4 = (f & 15) << 2;
        cp_async16(&Qs[r * QS_STR + d4], Qg + f * 4);
    }
    {
        uint32_t* Kb = sm4 + KS_OFF;
        uint32_t* Vb = sm4 + VS_OFF;
        #pragma unroll
        for (int j = 0; j < 8; j++) {
            int f = j * 128 + tid;
            int r = f >> 4, d4 = (f & 15) << 2;
            cp_async16(&Kb[r * KS_STR + d4], Kg + f * 4);
            cp_async16(&Vb[r * VS_STR + d4], Vg + f * 4);
        }
    }
    cp_commit();
    {
        uint32_t* Kb = sm4 + KS_OFF + 64 * KS_STR;
        uint32_t* Vb = sm4 + VS_OFF + 64 * VS_STR;
        #pragma unroll
        for (int j = 0; j < 8; j++) {
            int f = j * 128 + tid;
            int r = f >> 4, d4 = (f & 15) << 2;
            cp_async16(&Kb[r * KS_STR + d4], Kg + 64 * 64 + f * 4);
            cp_async16(&Vb[r * VS_STR + d4], Vg + 64 * 64 + f * 4);
        }
    }
    cp_commit();

    float o[2][8][4];
    float mstate[2][2], lstate[2][2];
    #pragma unroll
    for (int mt = 0; mt < 2; mt++) {
        mstate[mt][0] = -INFINITY; mstate[mt][1] = -INFINITY;
        lstate[mt][0] = 0.f;       lstate[mt][1] = 0.f;
        #pragma unroll
        for (int nt = 0; nt < 8; nt++)
            #pragma unroll
            for (int j = 0; j < 4; j++) o[mt][nt][j] = 0.f;
    }

    const int NIT = SEQ / 64;
    for (int it = 0; it < NIT; it++) {
        const int buf = it & 1;
        uint32_t* Ks = sm4 + KS_OFF + buf * 64 * KS_STR;
        uint32_t* Vs = sm4 + VS_OFF + buf * 64 * VS_STR;

        cp_wait1();
        __syncthreads();

        float sacc[2][8][4];
        #pragma unroll
        for (int mt = 0; mt < 2; mt++)
            #pragma unroll
            for (int nt = 0; nt < 8; nt++)
                #pragma unroll
                for (int j = 0; j < 4; j++) sacc[mt][nt][j] = 0.f;

        #pragma unroll
        for (int ks = 0; ks < 8; ks++) {
            const int ko = ks * 8 + t;
            uint32_t a[2][4];
            #pragma unroll
            for (int mt = 0; mt < 2; mt++) {
                const int r = base + mt * 16 + g;
                a[mt][0] = Qs[r * QS_STR + ko];
                a[mt][1] = Qs[(r + 8) * QS_STR + ko];
                a[mt][2] = Qs[r * QS_STR + ko + 4];
                a[mt][3] = Qs[(r + 8) * QS_STR + ko + 4];
            }
            #pragma unroll
            for (int nt = 0; nt < 8; nt++) {
                const int kr = nt * 8 + g;
                uint32_t b0 = Ks[kr * KS_STR + ko];
                uint32_t b1 = Ks[kr * KS_STR + ko + 4];
                mma8(sacc[0][nt], a[0], b0, b1);
                mma8(sacc[1][nt], a[1], b0, b1);
            }
        }

        #pragma unroll
        for (int mt = 0; mt < 2; mt++) {
            #pragma unroll
            for (int h = 0; h < 2; h++) {
                float mx = -INFINITY;
                #pragma unroll
                for (int nt = 0; nt < 8; nt++)
                    mx = fmaxf(mx, fmaxf(sacc[mt][nt][2 * h], sacc[mt][nt][2 * h + 1]));
                mx = fmaxf(mx, __shfl_xor_sync(0xffffffffu, mx, 1));
                mx = fmaxf(mx, __shfl_xor_sync(0xffffffffu, mx, 2));
                float mn = fmaxf(mstate[mt][h], mx);
                float alpha = ex2f(mstate[mt][h] - mn);
                float sum = 0.f;
                #pragma unroll
                for (int nt = 0; nt < 8; nt++) {
                    float p0 = tf32f(ex2f(sacc[mt][nt][2 * h] - mn));
                    float p1 = tf32f(ex2f(sacc[mt][nt][2 * h + 1] - mn));
                    sacc[mt][nt][2 * h]     = p0;
                    sacc[mt][nt][2 * h + 1] = p1;
                    sum += p0 + p1;
                }
                sum += __shfl_xor_sync(0xffffffffu, sum, 1);
                sum += __shfl_xor_sync(0xffffffffu, sum, 2);
                lstate[mt][h] = lstate[mt][h] * alpha + sum;
                mstate[mt][h] = mn;
                #pragma unroll
                for (int nt = 0; nt < 8; nt++) {
                    o[mt][nt][2 * h]     *= alpha;
                    o[mt][nt][2 * h + 1] *= alpha;
                }
            }
        }

        #pragma unroll
        for (int ks = 0; ks < 8; ks++) {
            uint32_t a0[4], a1[4];
            pfrag(sacc[0][ks], srcA, srcB, odd, a0);
            pfrag(sacc[1][ks], srcA, srcB, odd, a1);
            #pragma unroll
            for (int nt = 0; nt < 8; nt++) {
                uint32_t b0 = Vs[(ks * 8 + t) * VS_STR + nt * 8 + g];
                uint32_t b1 = Vs[(ks * 8 + t + 4) * VS_STR + nt * 8 + g];
                mma8(o[0][nt], a0, b0, b1);
                mma8(o[1][nt], a1, b0, b1);
            }
        }

        __syncthreads();

        if (it + 2 < NIT) {
            uint32_t* Kn = sm4 + KS_OFF + buf * 64 * KS_STR;
            uint32_t* Vn = sm4 + VS_OFF + buf * 64 * VS_STR;
            const float* Kp = Kg + (size_t)(it + 2) * 64 * 64;
            const float* Vp = Vg + (size_t)(it + 2) * 64 * 64;
            #pragma unroll
            for (int j = 0; j < 8; j++) {
                int f = j * 128 + tid;
                int r = f >> 4, d4 = (f & 15) << 2;
                cp_async16(&Kn[r * KS_STR + d4], Kp + f * 4);
                cp_async16(&Vn[r * VS_STR + d4], Vp + f * 4);
            }
        }
        cp_commit();
    }

    // epilogue: normalize, round to tf32 (proj GEMM input), write [b, n, h*64+d]
    const int b = bh / NHEAD, hh = bh % NHEAD;
    #pragma unroll
    for (int mt = 0; mt < 2; mt++) {
        #pragma unroll
        for (int h = 0; h < 2; h++) {
            const float inv = 1.0f / lstate[mt][h];
            const int n = q0 + base + mt * 16 + g + 8 * h;
            float* orow = Out + ((size_t)(b * SEQ + n)) * CDIM + hh * 64;
            #pragma unroll
            for (int nt = 0; nt < 8; nt++) {
                float2 v = { tf32f(o[mt][nt][2 * h] * inv),
                             tf32f(o[mt][nt][2 * h + 1] * inv) };
                *reinterpret_cast<float2*>(orow + nt * 8 + 2 * t) = v;
            }
        }
    }
}

// ------------------------------- launcher -------------------------------------
extern "C" void kernel_launch(void* const* d_in, const int* in_sizes, int n_in,
                              void* d_out, int out_size)
{
    const float* x        = (const float*)d_in[0];
    const float* rope_cos = (const float*)d_in[1];
    const float* rope_sin = (const float*)d_in[2];
    const float* qkv_k    = (const float*)d_in[3];
    const float* qkv_b    = (const float*)d_in[4];
    const float* proj_k   = (const float*)d_in[5];
    const float* proj_b   = (const float*)d_in[6];
    const float* qw       = (const float*)d_in[7];
    const float* kw       = (const float*)d_in[8];
    float* out = (float*)d_out;

    float *p_qkv, *p_q, *p_k, *p_v, *p_attn, *p_xr, *p_wqr, *p_wpr;
    cudaGetSymbolAddress((void**)&p_qkv,  g_qkv);
    cudaGetSymbolAddress((void**)&p_q,    g_q);
    cudaGetSymbolAddress((void**)&p_k,    g_k);
    cudaGetSymbolAddress((void**)&p_v,    g_v);
    cudaGetSymbolAddress((void**)&p_attn, g_attn);
    cudaGetSymbolAddress((void**)&p_xr,   g_xr);
    cudaGetSymbolAddress((void**)&p_wqr,  g_wqr);
    cudaGetSymbolAddress((void**)&p_wpr,  g_wpr);

    cudaFuncSetAttribute(sgemm_tf32, cudaFuncAttributeMaxDynamicSharedMemorySize, SG_SMEM);
    cudaFuncSetAttribute(flash_tf32, cudaFuncAttributeMaxDynamicSharedMemorySize,
                         FLASH_SMEM_BYTES);

    // 0) pre-round inputs to tf32
    round_tf32<<<(MROWS * CDIM / 4 + 255) / 256, 256>>>(x, p_xr, MROWS * CDIM / 4);
    round_tf32<<<(CDIM * QKVN / 4 + 255) / 256, 256>>>(qkv_k, p_wqr, CDIM * QKVN / 4);
    round_tf32<<<(CDIM * CDIM / 4 + 255) / 256, 256>>>(proj_k, p_wpr, CDIM * CDIM / 4);

    // 1) QKV GEMM
    {
        dim3 grid(QKVN / 128, MROWS / 128);
        sgemm_tf32<<<grid, 256, SG_SMEM>>>(MROWS, QKVN, CDIM, p_xr, p_wqr, qkv_b, p_qkv);
    }

    // 2) RMSNorm + RoPE + scatter
    {
        int warps = BATCH * SEQ * NHEAD;
        int blocks = (warps * 32 + 255) / 256;
        qkv_post<<<blocks, 256>>>(p_qkv, rope_cos, rope_sin, qw, kw, p_q, p_k, p_v);
    }

    // 3) flash attention (4 warps x 32 rows, 2 CTAs/SM — R8 config)
    {
        dim3 grid(SEQ / BQ, BHTOT);
        flash_tf32<<<grid, 128, FLASH_SMEM_BYTES>>>(p_q, p_k, p_v, p_attn);
    }

    // 4) projection GEMM
    {
        dim3 grid(CDIM / 128, MROWS / 128);
        sgemm_tf32<<<grid, 256, SG_SMEM>>>(MROWS, CDIM, CDIM, p_attn, p_wpr, proj_b, out);
    }
}

// round 13
// speedup vs baseline: 2.5738x; 1.5819x over previous
#include <cuda_runtime.h>
#include <cuda_fp16.h>
#include <stdint.h>
#include <math.h>

// Problem constants
#define BATCH 2
#define SEQ   2048
#define CDIM  768
#define NHEAD 12
#define HDIM  64
#define BHTOT (BATCH*NHEAD)          // 24
#define MROWS (BATCH*SEQ)            // 4096
#define QKVN  (3*CDIM)               // 2304

// ---------------- scratch (device globals; no allocation allowed) -------------
__device__ float  g_qkv[(size_t)MROWS * QKVN];           // QKV GEMM out (fp32)
__device__ __half g_xh[(size_t)MROWS * CDIM];            // x fp16 [M][K]
__device__ __half g_wqh[(size_t)QKVN * CDIM];            // qkv_kernel^T fp16 [N][K]
__device__ __half g_wph[(size_t)CDIM * CDIM];            // proj_kernel^T fp16 [N][K]
__device__ __half g_q[(size_t)BHTOT * SEQ * HDIM];       // [bh][n][d]
__device__ __half g_k[(size_t)BHTOT * SEQ * HDIM];       // [bh][n][d]
__device__ __half g_v[(size_t)BHTOT * HDIM * SEQ];       // [bh][d][n] (transposed)
__device__ __half g_attnh[(size_t)MROWS * CDIM];         // attention out fp16 [M][K]

// ---------------- helpers ------------------------------------------------------
__device__ __forceinline__ float ex2f(float x) {
    float y; asm("ex2.approx.f32 %0, %1;" : "=f"(y) : "f"(x)); return y;
}
// pack two fp32 -> f16x2 (lo in low half)
__device__ __forceinline__ uint32_t packh(float lo, float hi) {
    uint32_t u;
    asm("cvt.rn.f16x2.f32 %0, %1, %2;" : "=r"(u) : "f"(hi), "f"(lo));
    return u;
}
// mma m16n8k16 fp16 inputs, fp32 accum
__device__ __forceinline__ void mma16(float* c, const uint32_t* a, uint32_t b0, uint32_t b1) {
    asm volatile(
        "mma.sync.aligned.m16n8k16.row.col.f32.f16.f16.f32 "
        "{%0,%1,%2,%3}, {%4,%5,%6,%7}, {%8,%9}, {%0,%1,%2,%3};\n"
        : "+f"(c[0]), "+f"(c[1]), "+f"(c[2]), "+f"(c[3])
        : "r"(a[0]), "r"(a[1]), "r"(a[2]), "r"(a[3]), "r"(b0), "r"(b1));
}
__device__ __forceinline__ void cp_async16(void* dst_smem, const void* src_gmem) {
    uint32_t d = (uint32_t)__cvta_generic_to_shared(dst_smem);
    asm volatile("cp.async.cg.shared.global [%0], [%1], 16;\n" :: "r"(d), "l"(src_gmem));
}
__device__ __forceinline__ void cp_commit() { asm volatile("cp.async.commit_group;\n"); }
__device__ __forceinline__ void cp_wait1()  { asm volatile("cp.async.wait_group 1;\n"); }

// ---------------- prep kernels --------------------------------------------------
// elementwise fp32 -> fp16
__global__ __launch_bounds__(256) void conv_half(
    const float* __restrict__ src, __half* __restrict__ dst, int n4)
{
    int i = blockIdx.x * blockDim.x + threadIdx.x;
    if (i >= n4) return;
    float4 v = *reinterpret_cast<const float4*>(src + (size_t)i * 4);
    uint2 u;
    u.x = packh(v.x, v.y);
    u.y = packh(v.z, v.w);
    *reinterpret_cast<uint2*>(dst + (size_t)i * 4) = u;
}

// W [K][N] fp32 -> Wt [N][K] fp16 (transpose + convert)
__global__ __launch_bounds__(256) void convT_half(
    const float* __restrict__ W, __half* __restrict__ Wt, int K, int N)
{
    int idx = blockIdx.x * blockDim.x + threadIdx.x;
    if (idx >= N * (K >> 2)) return;
    int k = (idx / N) << 2;
    int n = idx - (idx / N) * N;
    float v0 = W[(size_t)(k + 0) * N + n];
    float v1 = W[(size_t)(k + 1) * N + n];
    float v2 = W[(size_t)(k + 2) * N + n];
    float v3 = W[(size_t)(k + 3) * N + n];
    uint2 u;
    u.x = packh(v0, v1);
    u.y = packh(v2, v3);
    *reinterpret_cast<uint2*>(Wt + (size_t)n * K + k) = u;
}

// ---------------- FP16 tensor-core GEMM + bias ----------------------------------
// C[M,N] = A[M,K] @ Bt[N,K]^T + bias, fp32 out. A,Bt fp16.
// BM=BN=128, BK=32, 256 thr (8 warps 2x4), warp tile 64x32, mma m16n8k16.
// smem tiles: A [128][40 halfs] (20 words/row), B [128][40 halfs]; 3 stages.
#define GW 20                          // words per tile row
#define STG_W (128*GW + 128*GW)        // 5120 words per stage
#define SG_SMEM (3*STG_W*4)            // 61440 B

__global__ __launch_bounds__(256, 2) void sgemm_fp16(
    int M, int N, int K,
    const __half* __restrict__ A, const __half* __restrict__ Bt,
    const float* __restrict__ bias, float* __restrict__ C)
{
    extern __shared__ uint32_t smw[];

    const int tid  = threadIdx.x;
    const int warp = tid >> 5;
    const int lane = tid & 31;
    const int g = lane >> 2, t = lane & 3;
    const int warp_m = warp >> 2;     // 0..1
    const int warp_n = warp & 3;      // 0..3
    const int brow = blockIdx.y, bcol = blockIdx.x;

    const __half* Ablk = A  + (size_t)brow * 128 * K;
    const __half* Bblk = Bt + (size_t)bcol * 128 * K;
    const int ktiles = K >> 5;

    float acc[4][4][4];
    #pragma unroll
    for (int mt = 0; mt < 4; mt++)
        #pragma unroll
        for (int nt = 0; nt < 4; nt++)
            #pragma unroll
            for (int j = 0; j < 4; j++) acc[mt][nt][j] = 0.f;

    auto stage = [&](int kt, int s) {
        uint32_t* As = smw + s * STG_W;
        uint32_t* Bs = As + 128 * GW;
        #pragma unroll
        for (int j = 0; j < 2; j++) {           // A: 512 chunks / 256 thr
            int f = j * 256 + tid;
            int r = f >> 2, q = f & 3;          // 4x16B per 64B row
            cp_async16(&As[r * GW + q * 4], Ablk + (size_t)r * K + kt * 32 + q * 8);
        }
        #pragma unroll
        for (int j = 0; j < 2; j++) {           // B: 512 chunks
            int f = j * 256 + tid;
            int r = f >> 2, q = f & 3;
            cp_async16(&Bs[r * GW + q * 4], Bblk + (size_t)r * K + kt * 32 + q * 8);
        }
    };

    stage(0, 0); cp_commit();
    stage(1, 1); cp_commit();

    for (int kt = 0; kt < ktiles; kt++) {
        cp_wait1();
        __syncthreads();
        if (kt + 2 < ktiles) stage(kt + 2, (kt + 2) % 3);
        cp_commit();   // empty group when no prefetch keeps wait_group(1) sound

        const uint32_t* As = smw + (kt % 3) * STG_W;
        const uint32_t* Bs = As + 128 * GW;

        #pragma unroll
        for (int s = 0; s < 2; s++) {           // two k16 steps per BK=32
            const int kw = s * 8 + t;
            uint32_t a[4][4], bf[4][2];
            #pragma unroll
            for (int mt = 0; mt < 4; mt++) {
                const int r = warp_m * 64 + mt * 16 + g;
                a[mt][0] = As[r * GW + kw];
                a[mt][1] = As[(r + 8) * GW + kw];
                a[mt][2] = As[r * GW + kw + 4];
                a[mt][3] = As[(r + 8) * GW + kw + 4];
            }
            #pragma unroll
            for (int nt = 0; nt < 4; nt++) {
                const int c = warp_n * 32 + nt * 8 + g;
                bf[nt][0] = Bs[c * GW + kw];
                bf[nt][1] = Bs[c * GW + kw + 4];
            }
            #pragma unroll
            for (int mt = 0; mt < 4; mt++)
                #pragma unroll
                for (int nt = 0; nt < 4; nt++)
                    mma16(acc[mt][nt], a[mt], bf[nt][0], bf[nt][1]);
        }
    }

    // epilogue: bias + fp32 store
    #pragma unroll
    for (int mt = 0; mt < 4; mt++) {
        const int r0 = brow * 128 + warp_m * 64 + mt * 16 + g;
        #pragma unroll
        for (int nt = 0; nt < 4; nt++) {
            const int c = bcol * 128 + warp_n * 32 + nt * 8 + 2 * t;
            float b0 = bias[c], b1 = bias[c + 1];
            float2 v0 = { acc[mt][nt][0] + b0, acc[mt][nt][1] + b1 };
            float2 v1 = { acc[mt][nt][2] + b0, acc[mt][nt][3] + b1 };
            *reinterpret_cast<float2*>(C + (size_t)r0 * N + c) = v0;
            *reinterpret_cast<float2*>(C + (size_t)(r0 + 8) * N + c) = v1;
        }
    }
}

// --------- QKV post: RMSNorm(q,k) + RoPE(q,k) + scale(q), scatter to fp16 -------
__global__ __launch_bounds__(256) void qkv_post(
    const float* __restrict__ qkv,
    const float* __restrict__ cosb, const float* __restrict__ sinb,
    const float* __restrict__ qw,   const float* __restrict__ kw,
    __half* __restrict__ Q, __half* __restrict__ K)
{
    int warp = (blockIdx.x * blockDim.x + threadIdx.x) >> 5;
    int lane = threadIdx.x & 31;
    const int NW = BATCH * SEQ * NHEAD;
    if (warp >= NW) return;
    int h = warp % NHEAD;
    int n = (warp / NHEAD) % SEQ;
    int b = warp / (NHEAD * SEQ);

    const float* row = qkv + (size_t)(b * SEQ + n) * QKVN;
    float q0 = row[h * 64 + lane],        q1 = row[h * 64 + lane + 32];
    float k0 = row[CDIM + h * 64 + lane], k1 = row[CDIM + h * 64 + lane + 32];

    float sq = q0 * q0 + q1 * q1;
    float sk = k0 * k0 + k1 * k1;
    #pragma unroll
    for (int o = 16; o > 0; o >>= 1) {
        sq += __shfl_xor_sync(0xffffffffu, sq, o);
        sk += __shfl_xor_sync(0xffffffffu, sk, o);
    }
    float rq = rsqrtf(sq * (1.0f / 64.0f) + 1e-6f);
    float rk = rsqrtf(sk * (1.0f / 64.0f) + 1e-6f);
    q0 *= rq * qw[lane]; q1 *= rq * qw[lane + 32];
    k0 *= rk * kw[lane]; k1 *= rk * kw[lane + 32];

    float c0 = cosb[n * 64 + lane], c1 = cosb[n * 64 + lane + 32];
    float s0 = sinb[n * 64 + lane], s1 = sinb[n * 64 + lane + 32];
    float qr0 = q0 * c0 - q1 * s0;
    float qr1 = q1 * c1 + q0 * s1;
    float kr0 = k0 * c0 - k1 * s0;
    float kr1 = k1 * c1 + k0 * s1;

    const float scale = 0.125f * 1.4426950408889634f;  // 1/sqrt(64) * log2(e)
    int bh = b * NHEAD + h;
    __half* qo = Q + ((size_t)bh * SEQ + n) * 64;
    __half* ko = K + ((size_t)bh * SEQ + n) * 64;
    qo[lane] = __float2half(qr0 * scale); qo[lane + 32] = __float2half(qr1 * scale);
    ko[lane] = __float2half(kr0);         ko[lane + 32] = __float2half(kr1);
}

// --------- V transpose: g_qkv V-slice [n][d] fp32 -> g_v [bh][d][n] fp16 ---------
__global__ __launch_bounds__(256) void v_trans(
    const float* __restrict__ qkv, __half* __restrict__ V)
{
    __shared__ __half tile[64][68];
    const int bh = blockIdx.y;
    const int h = bh % NHEAD, b = bh / NHEAD;
    const int n0 = blockIdx.x * 64;
    const int tid = threadIdx.x;

    #pragma unroll
    for (int i = 0; i < 16; i++) {
        int idx = i * 256 + tid;            // 0..4095
        int r = idx >> 6, c = idx & 63;     // r = n-local, c = d
        float v = qkv[(size_t)(b * SEQ + n0 + r) * QKVN + 2 * CDIM + h * 64 + c];
        tile[c][r] = __float2half(v);
    }
    __syncthreads();
    #pragma unroll
    for (int i = 0; i < 8; i++) {
        int idx = i * 256 + tid;            // 0..2047 half2 units
        int d = idx >> 5, n2 = (idx & 31) * 2;
        __half2 hv; hv.x = tile[d][n2]; hv.y = tile[d][n2 + 1];
        *reinterpret_cast<__half2*>(V + ((size_t)bh * 64 + d) * SEQ + n0 + n2) = hv;
    }
}

// ---------------- FP16 flash attention ------------------------------------------
// CTA: 128 threads (4 warps), Bq=128, Bk=64, d=64. Warp w owns rows [32w,32w+32).
// mma m16n8k16; PV A-frags are direct f16x2 packs of QK accumulators (no shfl).
// smem tiles 64-col halfs, stride 72 halfs (36 words): Q[128], K[2][64], Vt[2][64].
#define BQ 128
#define FW 36                               // words per tile row
#define QS_OFF 0
#define KS_OFF (128*FW)                     // 4608
#define VS_OFF (KS_OFF + 2*64*FW)           // 9216
#define FLASH_SMEM_WORDS (VS_OFF + 2*64*FW) // 13824
#define FLASH_SMEM_BYTES (FLASH_SMEM_WORDS * 4)  // 55296

__global__ __launch_bounds__(128, 2) void flash_fp16(
    const __half* __restrict__ Q, const __half* __restrict__ K,
    const __half* __restrict__ V, __half* __restrict__ Out)
{
    extern __shared__ uint32_t sm4[];
    uint32_t* Qs = sm4 + QS_OFF;

    const int bh = blockIdx.y;
    const int q0 = blockIdx.x * BQ;
    const int tid  = threadIdx.x;
    const int warp = tid >> 5;
    const int lane = tid & 31;
    const int g = lane >> 2, t = lane & 3;
    const int base = warp * 32;

    const __half* Qg = Q + ((size_t)bh * SEQ + q0) * 64;
    const __half* Kg = K + (size_t)bh * SEQ * 64;
    const __half* Vg = V + (size_t)bh * 64 * SEQ;   // [d][n]

    // prologue: stage Q + KV tile 0 (group 0), KV tile 1 (group 1)
    #pragma unroll
    for (int j = 0; j < 8; j++) {           // Q: 1024 chunks
        int f = j * 128 + tid;
        int r = f >> 3, c = f & 7;
        cp_async16(&Qs[r * FW + c * 4], Qg + r * 64 + c * 8);
    }
    #pragma unroll
    for (int bufp = 0; bufp < 2; bufp++) {
        uint32_t* Kb = sm4 + KS_OFF + bufp * 64 * FW;
        uint32_t* Vb = sm4 + VS_OFF + bufp * 64 * FW;
        #pragma unroll
        for (int j = 0; j < 4; j++) {       // K: 512 chunks
            int f = j * 128 + tid;
            int r = f >> 3, c = f & 7;
            cp_async16(&Kb[r * FW + c * 4], Kg + (size_t)(bufp * 64 + r) * 64 + c * 8);
        }
        #pragma unroll
        for (int j = 0; j < 4; j++) {       // V: 512 chunks (rows = d)
            int f = j * 128 + tid;
            int r = f >> 3, c = f & 7;
            cp_async16(&Vb[r * FW + c * 4], Vg + (size_t)r * SEQ + bufp * 64 + c * 8);
        }
        cp_commit();
    }

    float o[2][8][4];
    float mstate[2][2], lstate[2][2];
    #pragma unroll
    for (int mt = 0; mt < 2; mt++) {
        mstate[mt][0] = -INFINITY; mstate[mt][1] = -INFINITY;
        lstate[mt][0] = 0.f;       lstate[mt][1] = 0.f;
        #pragma unroll
        for (int nt = 0; nt < 8; nt++)
            #pragma unroll
            for (int j = 0; j < 4; j++) o[mt][nt][j] = 0.f;
    }

    const int NIT = SEQ / 64;  // 32
    for (int it = 0; it < NIT; it++) {
        const int buf = it & 1;
        uint32_t* Ks = sm4 + KS_OFF + buf * 64 * FW;
        uint32_t* Vs = sm4 + VS_OFF + buf * 64 * FW;

        cp_wait1();
        __syncthreads();

        // ---- S = Q K^T (log2-scaled) ----
        float sacc[2][8][4];
        #pragma unroll
        for (int mt = 0; mt < 2; mt++)
            #pragma unroll
            for (int nt = 0; nt < 8; nt++)
                #pragma unroll
                for (int j = 0; j < 4; j++) sacc[mt][nt][j] = 0.f;

        #pragma unroll
        for (int j = 0; j < 4; j++) {       // k16 steps over d=64
            const int kw = j * 8 + t;
            uint32_t a[2][4];
            #pragma unroll
            for (int mt = 0; mt < 2; mt++) {
                const int r = base + mt * 16 + g;
                a[mt][0] = Qs[r * FW + kw];
                a[mt][1] = Qs[(r + 8) * FW + kw];
                a[mt][2] = Qs[r * FW + kw + 4];
                a[mt][3] = Qs[(r + 8) * FW + kw + 4];
            }
            #pragma unroll
            for (int nt = 0; nt < 8; nt++) {
                const int kr = nt * 8 + g;
                uint32_t b0 = Ks[kr * FW + kw];
                uint32_t b1 = Ks[kr * FW + kw + 4];
                mma16(sacc[0][nt], a[0], b0, b1);
                mma16(sacc[1][nt], a[1], b0, b1);
            }
        }

        // ---- online softmax (exp2 domain), p in fp32 registers ----
        #pragma unroll
        for (int mt = 0; mt < 2; mt++) {
            #pragma unroll
            for (int h = 0; h < 2; h++) {
                float mx = -INFINITY;
                #pragma unroll
                for (int nt = 0; nt < 8; nt++)
                    mx = fmaxf(mx, fmaxf(sacc[mt][nt][2 * h], sacc[mt][nt][2 * h + 1]));
                mx = fmaxf(mx, __shfl_xor_sync(0xffffffffu, mx, 1));
                mx = fmaxf(mx, __shfl_xor_sync(0xffffffffu, mx, 2));
                float mn = fmaxf(mstate[mt][h], mx);
                float alpha = ex2f(mstate[mt][h] - mn);
                float sum = 0.f;
                #pragma unroll
                for (int nt = 0; nt < 8; nt++) {
                    float p0 = ex2f(sacc[mt][nt][2 * h] - mn);
                    float p1 = ex2f(sacc[mt][nt][2 * h + 1] - mn);
                    sacc[mt][nt][2 * h]     = p0;
                    sacc[mt][nt][2 * h + 1] = p1;
                    sum += p0 + p1;
                }
                sum += __shfl_xor_sync(0xffffffffu, sum, 1);
                sum += __shfl_xor_sync(0xffffffffu, sum, 2);
                lstate[mt][h] = lstate[mt][h] * alpha + sum;
                mstate[mt][h] = mn;
                #pragma unroll
                for (int nt = 0; nt < 8; nt++) {
                    o[mt][nt][2 * h]     *= alpha;
                    o[mt][nt][2 * h + 1] *= alpha;
                }
            }
        }

        // ---- O += P V  (P A-frags = f16x2 packs of sacc; V via smem) ----
        #pragma unroll
        for (int j = 0; j < 4; j++) {       // k16 steps over 64 keys
            const int kw = j * 8 + t;
            uint32_t a[2][4];
            #pragma unroll
            for (int mt = 0; mt < 2; mt++) {
                a[mt][0] = packh(sacc[mt][2 * j][0],     sacc[mt][2 * j][1]);
                a[mt][1] = packh(sacc[mt][2 * j][2],     sacc[mt][2 * j][3]);
                a[mt][2] = packh(sacc[mt][2 * j + 1][0], sacc[mt][2 * j + 1][1]);
                a[mt][3] = packh(sacc[mt][2 * j + 1][2], sacc[mt][2 * j + 1][3]);
            }
            #pragma unroll
            for (int nt = 0; nt < 8; nt++) {
                const int vr = nt * 8 + g;
                uint32_t b0 = Vs[vr * FW + kw];
                uint32_t b1 = Vs[vr * FW + kw + 4];
                mma16(o[0][nt], a[0], b0, b1);
                mma16(o[1][nt], a[1], b0, b1);
            }
        }

        __syncthreads();  // all warps done with this K/V buffer

        // stage KV tile it+2 into this buffer
        if (it + 2 < NIT) {
            uint32_t* Kn = sm4 + KS_OFF + buf * 64 * FW;
            uint32_t* Vn = sm4 + VS_OFF + buf * 64 * FW;
            const __half* Kp = Kg + (size_t)(it + 2) * 64 * 64;
            const int ncol = (it + 2) * 64;
            #pragma unroll
            for (int j = 0; j < 4; j++) {
                int f = j * 128 + tid;
                int r = f >> 3, c = f & 7;
                cp_async16(&Kn[r * FW + c * 4], Kp + (size_t)r * 64 + c * 8);
            }
            #pragma unroll
            for (int j = 0; j < 4; j++) {
                int f = j * 128 + tid;
                int r = f >> 3, c = f & 7;
                cp_async16(&Vn[r * FW + c * 4], Vg + (size_t)r * SEQ + ncol + c * 8);
            }
        }
        cp_commit();
    }

    // ---- epilogue: normalize, write fp16 [b, n, h*64+d] (proj GEMM A input) ----
    const int b = bh / NHEAD, hh = bh % NHEAD;
    #pragma unroll
    for (int mt = 0; mt < 2; mt++) {
        #pragma unroll
        for (int h = 0; h < 2; h++) {
            const float inv = 1.0f / lstate[mt][h];
            const int n = q0 + base + mt * 16 + g + 8 * h;
            __half* orow = Out + ((size_t)(b * SEQ + n)) * CDIM + hh * 64;
            #pragma unroll
            for (int nt = 0; nt < 8; nt++) {
                uint32_t u = packh(o[mt][nt][2 * h] * inv, o[mt][nt][2 * h + 1] * inv);
                *reinterpret_cast<uint32_t*>(orow + nt * 8 + 2 * t) = u;
            }
        }
    }
}

// ------------------------------- launcher -------------------------------------
extern "C" void kernel_launch(void* const* d_in, const int* in_sizes, int n_in,
                              void* d_out, int out_size)
{
    const float* x        = (const float*)d_in[0];
    const float* rope_cos = (const float*)d_in[1];
    const float* rope_sin = (const float*)d_in[2];
    const float* qkv_k    = (const float*)d_in[3];
    const float* qkv_b    = (const float*)d_in[4];
    const float* proj_k   = (const float*)d_in[5];
    const float* proj_b   = (const float*)d_in[6];
    const float* qw       = (const float*)d_in[7];
    const float* kw       = (const float*)d_in[8];
    float* out = (float*)d_out;

    float *p_qkv;
    __half *p_xh, *p_wqh, *p_wph, *p_q, *p_k, *p_v, *p_attnh;
    cudaGetSymbolAddress((void**)&p_qkv,   g_qkv);
    cudaGetSymbolAddress((void**)&p_xh,    g_xh);
    cudaGetSymbolAddress((void**)&p_wqh,   g_wqh);
    cudaGetSymbolAddress((void**)&p_wph,   g_wph);
    cudaGetSymbolAddress((void**)&p_q,     g_q);
    cudaGetSymbolAddress((void**)&p_k,     g_k);
    cudaGetSymbolAddress((void**)&p_v,     g_v);
    cudaGetSymbolAddress((void**)&p_attnh, g_attnh);

    cudaFuncSetAttribute(sgemm_fp16, cudaFuncAttributeMaxDynamicSharedMemorySize, SG_SMEM);
    cudaFuncSetAttribute(flash_fp16, cudaFuncAttributeMaxDynamicSharedMemorySize,
                         FLASH_SMEM_BYTES);

    // 0) preps: x -> fp16; weights -> transposed fp16
    conv_half<<<(MROWS * CDIM / 4 + 255) / 256, 256>>>(x, p_xh, MROWS * CDIM / 4);
    convT_half<<<(QKVN * (CDIM / 4) + 255) / 256, 256>>>(qkv_k, p_wqh, CDIM, QKVN);
    convT_half<<<(CDIM * (CDIM / 4) + 255) / 256, 256>>>(proj_k, p_wph, CDIM, CDIM);

    // 1) QKV GEMM: [4096,768] x [768,2304] -> fp32
    {
        dim3 grid(QKVN / 128, MROWS / 128);
        sgemm_fp16<<<grid, 256, SG_SMEM>>>(MROWS, QKVN, CDIM, p_xh, p_wqh, qkv_b, p_qkv);
    }

    // 2) RMSNorm + RoPE + scatter (Q,K fp16) ; V transpose to [bh][d][n] fp16
    {
        int warps = BATCH * SEQ * NHEAD;
        int blocks = (warps * 32 + 255) / 256;
        qkv_post<<<blocks, 256>>>(p_qkv, rope_cos, rope_sin, qw, kw, p_q, p_k);
        dim3 vgrid(SEQ / 64, BHTOT);
        v_trans<<<vgrid, 256>>>(p_qkv, p_v);
    }

    // 3) flash attention (fp16 mma, 4 warps x 32 rows)
    {
        dim3 grid(SEQ / BQ, BHTOT);
        flash_fp16<<<grid, 128, FLASH_SMEM_BYTES>>>(p_q, p_k, p_v, p_attnh);
    }

    // 4) projection GEMM: [4096,768] x [768,768] -> d_out fp32
    {
        dim3 grid(CDIM / 128, MROWS / 128);
        sgemm_fp16<<<grid, 256, SG_SMEM>>>(MROWS, CDIM, CDIM, p_attnh, p_wph, proj_b, out);
    }
}